// round 1
// baseline (speedup 1.0000x reference)
#include <cuda_runtime.h>
#include <cstdint>

#define NN   200000
#define DIM  20
#define EE   6400000
#define ITERS 3

// Persistent scratch (allocations are banned; __device__ globals are the workaround)
__device__ __align__(16) float g_h[(size_t)NN * DIM];
__device__ __align__(16) float g_x[(size_t)NN * DIM];

// ---------------------------------------------------------------------------
// init: copy input h into scratch, zero x
// ---------------------------------------------------------------------------
__global__ void init_kernel(const float* __restrict__ h_in) {
    int i = blockIdx.x * blockDim.x + threadIdx.x;
    const int n4 = NN * DIM / 4;
    if (i < n4) {
        reinterpret_cast<float4*>(g_h)[i] = reinterpret_cast<const float4*>(h_in)[i];
        reinterpret_cast<float4*>(g_x)[i] = make_float4(0.f, 0.f, 0.f, 0.f);
    }
}

__global__ void zero_x_kernel() {
    int i = blockIdx.x * blockDim.x + threadIdx.x;
    const int n4 = NN * DIM / 4;
    if (i < n4)
        reinterpret_cast<float4*>(g_x)[i] = make_float4(0.f, 0.f, 0.f, 0.f);
}

// ---------------------------------------------------------------------------
// scatter: x[dst] += h[src] for edges with depth[src]<=thr && depth[dst]<=thr
// ---------------------------------------------------------------------------
__device__ __forceinline__ void red_add_v4(float* p, float4 v) {
    unsigned long long ga = (unsigned long long)__cvta_generic_to_global((void*)p);
    asm volatile("red.global.add.v4.f32 [%0], {%1,%2,%3,%4};"
                 :: "l"(ga), "f"(v.x), "f"(v.y), "f"(v.z), "f"(v.w)
                 : "memory");
}

__global__ void scatter_kernel(const int* __restrict__ esrc,
                               const int* __restrict__ edst,
                               const int* __restrict__ depth,
                               int thr) {
    int e = blockIdx.x * blockDim.x + threadIdx.x;
    if (e >= EE) return;
    int s = __ldg(esrc + e);
    int d = __ldg(edst + e);
    if (__ldg(depth + s) > thr) return;
    if (__ldg(depth + d) > thr) return;

    const float4* hp = reinterpret_cast<const float4*>(g_h + (size_t)s * DIM);
    float4 v0 = hp[0], v1 = hp[1], v2 = hp[2], v3 = hp[3], v4 = hp[4];

    float* xp = g_x + (size_t)d * DIM;
    red_add_v4(xp + 0,  v0);
    red_add_v4(xp + 4,  v1);
    red_add_v4(xp + 8,  v2);
    red_add_v4(xp + 12, v3);
    red_add_v4(xp + 16, v4);
}

// ---------------------------------------------------------------------------
// GRU update per node
// ---------------------------------------------------------------------------
struct WParams {
    const float* W[6];   // Wz, Uz, Wr, Ur, Wh, Uh   (each [DIM,DIM], row = out)
    const float* B[6];   // bz, buz, br, bur, bh, buh
};

__device__ __forceinline__ float fsigmoid(float v) {
    return 1.f / (1.f + __expf(-v));
}

__global__ void gru_kernel(const int* __restrict__ depth, int thr,
                           WParams p, float* __restrict__ out_final) {
    __shared__ __align__(16) float sW[6 * DIM * DIM];
    __shared__ float sB[6 * DIM];

    for (int t = threadIdx.x; t < 6 * DIM * DIM; t += blockDim.x)
        sW[t] = p.W[t / (DIM * DIM)][t % (DIM * DIM)];
    for (int t = threadIdx.x; t < 6 * DIM; t += blockDim.x)
        sB[t] = p.B[t / DIM][t % DIM];
    __syncthreads();

    int u = blockIdx.x * blockDim.x + threadIdx.x;
    if (u >= NN) return;

    bool act = (__ldg(depth + u) <= thr);
    if (!act) {
        if (out_final) {
            float4* o = reinterpret_cast<float4*>(out_final + (size_t)u * DIM);
            float4 z4 = make_float4(0.f, 0.f, 0.f, 0.f);
            o[0] = z4; o[1] = z4; o[2] = z4; o[3] = z4; o[4] = z4;
        }
        return;   // h unchanged for inactive nodes
    }

    const float* Wz = sW + 0    * DIM * DIM;
    const float* Uz = sW + 1    * DIM * DIM;
    const float* Wr = sW + 2    * DIM * DIM;
    const float* Ur = sW + 3    * DIM * DIM;
    const float* Wh = sW + 4    * DIM * DIM;
    const float* Uh = sW + 5    * DIM * DIM;
    const float* bz  = sB + 0 * DIM;
    const float* buz = sB + 1 * DIM;
    const float* br  = sB + 2 * DIM;
    const float* bur = sB + 3 * DIM;
    const float* bh  = sB + 4 * DIM;
    const float* buh = sB + 5 * DIM;

    float xv[DIM], hv[DIM];
    {
        const float4* xp = reinterpret_cast<const float4*>(g_x + (size_t)u * DIM);
        const float4* hp = reinterpret_cast<const float4*>(g_h + (size_t)u * DIM);
#pragma unroll
        for (int k = 0; k < 5; k++) {
            float4 a = xp[k];
            xv[4*k+0] = a.x; xv[4*k+1] = a.y; xv[4*k+2] = a.z; xv[4*k+3] = a.w;
            float4 b = hp[k];
            hv[4*k+0] = b.x; hv[4*k+1] = b.y; hv[4*k+2] = b.z; hv[4*k+3] = b.w;
        }
    }

    // r gate -> q = r * h
    float q[DIM];
#pragma unroll
    for (int j = 0; j < DIM; j++) {
        float s = br[j] + bur[j];
        const float4* wr = reinterpret_cast<const float4*>(Wr + j * DIM);
        const float4* ur = reinterpret_cast<const float4*>(Ur + j * DIM);
#pragma unroll
        for (int k = 0; k < 5; k++) {
            float4 w = wr[k], uu = ur[k];
            s += w.x  * xv[4*k+0] + w.y  * xv[4*k+1] + w.z  * xv[4*k+2] + w.w  * xv[4*k+3];
            s += uu.x * hv[4*k+0] + uu.y * hv[4*k+1] + uu.z * hv[4*k+2] + uu.w * hv[4*k+3];
        }
        q[j] = fsigmoid(s) * hv[j];
    }

    // z gate + candidate + blend
    float onew[DIM];
#pragma unroll
    for (int j = 0; j < DIM; j++) {
        float sz = bz[j] + buz[j];
        float sh = bh[j] + buh[j];
        const float4* wz = reinterpret_cast<const float4*>(Wz + j * DIM);
        const float4* uz = reinterpret_cast<const float4*>(Uz + j * DIM);
        const float4* wh = reinterpret_cast<const float4*>(Wh + j * DIM);
        const float4* uh = reinterpret_cast<const float4*>(Uh + j * DIM);
#pragma unroll
        for (int k = 0; k < 5; k++) {
            float4 a = wz[k], b = uz[k], c = wh[k], d = uh[k];
            sz += a.x * xv[4*k+0] + a.y * xv[4*k+1] + a.z * xv[4*k+2] + a.w * xv[4*k+3];
            sz += b.x * hv[4*k+0] + b.y * hv[4*k+1] + b.z * hv[4*k+2] + b.w * hv[4*k+3];
            sh += c.x * xv[4*k+0] + c.y * xv[4*k+1] + c.z * xv[4*k+2] + c.w * xv[4*k+3];
            sh += d.x * q [4*k+0] + d.y * q [4*k+1] + d.z * q [4*k+2] + d.w * q [4*k+3];
        }
        float z  = fsigmoid(sz);
        float hc = tanhf(sh);
        onew[j] = z * hv[j] + (1.f - z) * hc;
    }

    float* dst = out_final ? (out_final + (size_t)u * DIM) : (g_h + (size_t)u * DIM);
    float4* d4 = reinterpret_cast<float4*>(dst);
#pragma unroll
    for (int k = 0; k < 5; k++)
        d4[k] = make_float4(onew[4*k+0], onew[4*k+1], onew[4*k+2], onew[4*k+3]);
}

// ---------------------------------------------------------------------------
// launch
// ---------------------------------------------------------------------------
extern "C" void kernel_launch(void* const* d_in, const int* in_sizes, int n_in,
                              void* d_out, int out_size) {
    // Identify inputs by element count (robust to metadata ordering):
    //   N*DIM -> h, N -> node2depth, E (x2, in order) -> edge_src, edge_dst,
    //   400 (x6, in order) -> Wz,Uz,Wr,Ur,Wh,Uh, 20 (x6, in order) -> biases.
    const float* h_in = nullptr;
    const int*   depth = nullptr;
    const int*   esrc = nullptr;
    const int*   edst = nullptr;
    const float* Ws[6] = {};
    const float* Bs[6] = {};
    int wi = 0, bi = 0, ei = 0;
    for (int i = 0; i < n_in; i++) {
        int s = in_sizes[i];
        if (s == NN * DIM)      h_in  = (const float*)d_in[i];
        else if (s == NN)       depth = (const int*)d_in[i];
        else if (s == EE) {
            if (ei == 0) esrc = (const int*)d_in[i];
            else         edst = (const int*)d_in[i];
            ei++;
        }
        else if (s == DIM * DIM && wi < 6) Ws[wi++] = (const float*)d_in[i];
        else if (s == DIM      && bi < 6)  Bs[bi++] = (const float*)d_in[i];
    }

    WParams p;
    for (int m = 0; m < 6; m++) { p.W[m] = Ws[m]; p.B[m] = Bs[m]; }

    float* out = (float*)d_out;

    const int n4       = NN * DIM / 4;
    const int cb_init  = (n4 + 255) / 256;
    const int cb_edge  = (EE + 255) / 256;
    const int cb_node  = (NN + 255) / 256;

    init_kernel<<<cb_init, 256>>>(h_in);

    for (int i = 0; i < ITERS; i++) {
        int thr = ITERS - i;   // active: depth + i <= ITERS  <=>  depth <= ITERS - i
        scatter_kernel<<<cb_edge, 256>>>(esrc, edst, depth, thr);
        gru_kernel<<<cb_node, 256>>>(depth, thr, p,
                                     (i == ITERS - 1) ? out : nullptr);
        if (i < ITERS - 1)
            zero_x_kernel<<<cb_init, 256>>>();
    }
}